// round 14
// baseline (speedup 1.0000x reference)
#include <cuda_runtime.h>
#include <cstdint>
#include <cstddef>

#define BB 64
#define TT 512
#define II 128
#define HH 512
#define NCLS 5

#define F_HAVEA 1
#define F_HAVEB 2
#define F_GATEA 4

#define TTHH ((size_t)TT * HH)
#define CH_STRIDE 1040u            // padded chunk stride (bytes): 1KB data + 16B pad
#define BUF_STRIDE (8u * CH_STRIDE)        // 8320
#define GRP_STRIDE (2u * BUF_STRIDE)       // 16640
#define HS_BYTES   (2u * GRP_STRIDE)       // 33280

typedef unsigned long long u64;
typedef ulonglong2 ull2;

// Scratch — static __device__ arrays per allocation rules.
__device__ float g_xpA[(size_t)BB * TT * HH];
__device__ float g_xpB[(size_t)BB * TT * HH];
__device__ float g_ys[(size_t)BB * TT * HH];

// Cross-CTA coordination (reset by reset_counters before every mega launch).
__device__ int g_jcA;        // phase-A job queue head
__device__ int g_jcB;        // phase-B job queue head
__device__ int g_dA[4];      // phase-A completed-jobs count per t-block
__device__ int g_prog[64];   // recurrence progress per (cluster, rank)

// ---------------- packed f32x2 helpers ----------------
__device__ __forceinline__ u64 pk2(float x, float y) {
    u64 r; asm("mov.b64 %0, {%1,%2};" : "=l"(r) : "f"(x), "f"(y)); return r;
}
__device__ __forceinline__ float2 upk2(u64 v) {
    float2 f; asm("mov.b64 {%0,%1}, %2;" : "=f"(f.x), "=f"(f.y) : "l"(v)); return f;
}
__device__ __forceinline__ void fma2(u64 &d, u64 a, u64 b) {
    asm("fma.rn.f32x2 %0, %1, %2, %0;" : "+l"(d) : "l"(a), "l"(b));
}

// ---------------- cluster / mbarrier helpers ----------------
__device__ __forceinline__ uint32_t smem_u32(const void* p) {
    uint32_t a;
    asm("{ .reg .u64 t; cvta.to.shared.u64 t, %1; cvt.u32.u64 %0, t; }"
        : "=r"(a) : "l"(p));
    return a;
}
__device__ __forceinline__ uint32_t mapa_u32(uint32_t local, uint32_t rank) {
    uint32_t r;
    asm("mapa.shared::cluster.u32 %0, %1, %2;" : "=r"(r) : "r"(local), "r"(rank));
    return r;
}
__device__ __forceinline__ void mbar_init(uint32_t addr, uint32_t count) {
    asm volatile("mbarrier.init.shared.b64 [%0], %1;" :: "r"(addr), "r"(count) : "memory");
}
__device__ __forceinline__ void mbar_expect_tx(uint32_t addr, uint32_t bytes) {
    asm volatile("mbarrier.arrive.expect_tx.shared.b64 _, [%0], %1;"
                 :: "r"(addr), "r"(bytes) : "memory");
}
__device__ __forceinline__ void bulk_copy_cluster(uint32_t dst_cluster, uint32_t src_cta,
                                                  uint32_t bytes, uint32_t mbar_cluster) {
    asm volatile("cp.async.bulk.shared::cluster.shared::cta.mbarrier::complete_tx::bytes "
                 "[%0], [%1], %2, [%3];"
                 :: "r"(dst_cluster), "r"(src_cta), "r"(bytes), "r"(mbar_cluster) : "memory");
}
__device__ __forceinline__ void mbar_wait_cluster(uint32_t addr, uint32_t parity) {
    asm volatile(
        "{\n\t"
        ".reg .pred P;\n\t"
        "WLP%=:\n\t"
        "mbarrier.try_wait.parity.acquire.cluster.shared::cta.b64 P, [%0], %1, 0x989680;\n\t"
        "@P bra WDN%=;\n\t"
        "bra WLP%=;\n\t"
        "WDN%=:\n\t"
        "}"
        :: "r"(addr), "r"(parity) : "memory");
}
__device__ __forceinline__ void fence_proxy_async_cta() {
    asm volatile("fence.proxy.async.shared::cta;" ::: "memory");
}
__device__ __forceinline__ void cluster_sync_full() {
    asm volatile("barrier.cluster.arrive.aligned;" ::: "memory");
    asm volatile("barrier.cluster.wait.aligned;" ::: "memory");
}

// =======================================================================
// One 128x128 GEMM tile: C = A[0:128,0:K] @ W[0:128,0:K]^T + b1 + b2.
// =======================================================================
__device__ __forceinline__ void gemm_tile(
    const float* __restrict__ A, const float* __restrict__ W,
    const float* __restrict__ b1, const float* __restrict__ b2,
    float* __restrict__ C, int K,
    u64 (*As2)[128], u64 (*Bs2)[128])
{
    const int tid = threadIdx.x;
    const int tx = tid & 15;
    const int ty = tid >> 4;
    const int r0  = tid >> 2;
    const int kq0 = tid & 3;

    u64 acc[8][8];
    #pragma unroll
    for (int i = 0; i < 8; i++)
        #pragma unroll
        for (int j = 0; j < 8; j++) acc[i][j] = 0ull;

    const float* pa0 = &A[(size_t)r0        * K + kq0 * 4];
    const float* pa1 = &A[(size_t)(64 + r0) * K + kq0 * 4];
    const float* pw0 = &W[(size_t)r0        * K + kq0 * 4];
    const float* pw1 = &W[(size_t)(64 + r0) * K + kq0 * 4];

    const int ktiles = K >> 4;
    float4 a0 = *(const float4*)pa0;
    float4 a1 = *(const float4*)pa1;
    float4 w0 = *(const float4*)pw0;
    float4 w1 = *(const float4*)pw1;

    for (int kt = 0; kt < ktiles; kt++) {
        __syncthreads();
        As2[kq0 * 2][r0]          = pk2(a0.x, a0.y);
        As2[kq0 * 2 + 1][r0]      = pk2(a0.z, a0.w);
        As2[kq0 * 2][64 + r0]     = pk2(a1.x, a1.y);
        As2[kq0 * 2 + 1][64 + r0] = pk2(a1.z, a1.w);
        Bs2[kq0 * 2][r0]          = pk2(w0.x, w0.y);
        Bs2[kq0 * 2 + 1][r0]      = pk2(w0.z, w0.w);
        Bs2[kq0 * 2][64 + r0]     = pk2(w1.x, w1.y);
        Bs2[kq0 * 2 + 1][64 + r0] = pk2(w1.z, w1.w);
        __syncthreads();

        if (kt + 1 < ktiles) {
            const int kb = (kt + 1) * 16;
            a0 = *(const float4*)(pa0 + kb);
            a1 = *(const float4*)(pa1 + kb);
            w0 = *(const float4*)(pw0 + kb);
            w1 = *(const float4*)(pw1 + kb);
        }

        #pragma unroll
        for (int k2 = 0; k2 < 8; k2++) {
            u64 af[8], bf[8];
            #pragma unroll
            for (int i = 0; i < 8; i++) af[i] = As2[k2][ty + 16 * i];
            #pragma unroll
            for (int j = 0; j < 8; j++) bf[j] = Bs2[k2][tx + 16 * j];
            #pragma unroll
            for (int i = 0; i < 8; i++)
                #pragma unroll
                for (int j = 0; j < 8; j++)
                    fma2(acc[i][j], af[i], bf[j]);
        }
    }

    float bias8[8];
    #pragma unroll
    for (int j = 0; j < 8; j++) {
        int n = tx + 16 * j;
        bias8[j] = b1[n] + b2[n];
    }
    #pragma unroll
    for (int i = 0; i < 8; i++) {
        const size_t m = (size_t)(ty + 16 * i);
        #pragma unroll
        for (int j = 0; j < 8; j++) {
            float2 p = upk2(acc[i][j]);
            C[m * HH + tx + 16 * j] = p.x + p.y + bias8[j];
        }
    }
}

// Run phase-B jobs (xproj of next layer from ys, K=512, gated on g_prog).
__device__ void run_phaseB(const float* __restrict__ ys,
                           const float* __restrict__ WihB,
                           const float* __restrict__ biB,
                           const float* __restrict__ bhB,
                           float* __restrict__ CB,
                           u64 (*As2)[128], u64 (*Bs2)[128])
{
    __shared__ int s_job;
    for (;;) {
        if (threadIdx.x == 0)
            s_job = atomicAdd(&g_jcB, 1);
        __syncthreads();
        const int j = s_job;
        if (j >= 1024) break;
        const int tb = j >> 8, r8 = j & 255, b = r8 >> 2, nt = r8 & 3;
        const int thr = tb * 128 + 128;
        if (threadIdx.x == 0) {
            const int cb8 = (b >> 3) * 8;
            #pragma unroll
            for (int q = 0; q < 8; q++) {
                while (((volatile int*)g_prog)[cb8 + q] < thr)
                    __nanosleep(128);
            }
            __threadfence();
        }
        __syncthreads();
        gemm_tile(ys + (size_t)(b * TT + tb * 128) * HH,
                  WihB + (size_t)(nt * 128) * HH,
                  biB + nt * 128, bhB + nt * 128,
                  CB + (size_t)(b * TT + tb * 128) * HH + nt * 128,
                  HH, As2, Bs2);
        __syncthreads();
    }
}

// =======================================================================
// Mega kernel: clusters 0..7 = recurrence; clusters >= 8 = GEMM workers.
// Recurrence: column-partitioned warps, in-warp shuffle reduction, R9
// bulk-engine exchange, one mbar per (group, buf) with expect_tx 8192.
// =======================================================================
__global__ void __launch_bounds__(256, 1) __cluster_dims__(8, 1, 1)
mega(const float* __restrict__ xp, const float* __restrict__ Whh,
     float* __restrict__ ys,
     const float* __restrict__ Ax,  const float* __restrict__ WihA,
     const float* __restrict__ biA, const float* __restrict__ bhA,
     float* __restrict__ CA, int KA,
     const float* __restrict__ WihB, const float* __restrict__ biB,
     const float* __restrict__ bhB,  float* __restrict__ CB,
     int flags)
{
    __shared__ __align__(16) char hbuf[HS_BYTES];           // [g][buf][chunk(1040B)]
    __shared__ __align__(16) float out_s[2][2][4][64];      // [g][buf][batch][col]
    __shared__ __align__(8) u64 mbar[4];                    // [g*2+buf]
    __shared__ u64 As2[8][128];
    __shared__ u64 Bs2[8][128];

    const int tid = threadIdx.x;
    const int cl  = blockIdx.x >> 3;

    if (cl >= 8) {
        // ======================= GEMM role =======================
        if (flags & F_HAVEA) {
            __shared__ int s_job;
            for (;;) {
                if (tid == 0) s_job = atomicAdd(&g_jcA, 1);
                __syncthreads();
                const int j = s_job;
                if (j >= 1024) break;
                const int tb = j >> 8, r8 = j & 255, b = r8 >> 2, nt = r8 & 3;
                gemm_tile(Ax + (size_t)(b * TT + tb * 128) * KA,
                          WihA + (size_t)(nt * 128) * KA,
                          biA + nt * 128, bhA + nt * 128,
                          CA + (size_t)(b * TT + tb * 128) * HH + nt * 128,
                          KA, As2, Bs2);
                __syncthreads();
                __threadfence();
                if (tid == 0) atomicAdd(&g_dA[tb], 1);
                __syncthreads();
            }
        }
        if (flags & F_HAVEB)
            run_phaseB(ys, WihB, biB, bhB, CB, As2, Bs2);
        return;
    }

    // ======================= recurrence role =======================
    const int r     = blockIdx.x & 7;
    const int bg    = cl * 8;
    const int jbase = r * 64;
    const bool gateA = (flags & F_GATEA) != 0;

    const int wj  = tid >> 5;          // warp = column group
    const int jp  = tid & 31;
    const int c8  = jp >> 2;           // col within group (0..7)
    const int kq  = jp & 3;            // k quarter (0..3)
    const int col = wj * 8 + c8;       // local col 0..63
    const bool lead = (kq == 0);

    // ---- W: 64 k-pairs for (col, 128-wide k window kq) ----
    u64 w[64];
    {
        const float* wrow = &Whh[(size_t)(jbase + col) * HH + kq * 128];
        #pragma unroll
        for (int i = 0; i < 32; i++) {
            float4 v = *(const float4*)&wrow[i * 4];
            w[2 * i]     = pk2(v.x, v.y);
            w[2 * i + 1] = pk2(v.z, v.w);
        }
    }

    // ---- zero h buffers; init 4 mbarriers (count 1) + first expects ----
    {
        float4* hz = (float4*)hbuf;
        for (int i = tid; i < (int)(HS_BYTES / 16); i += 256)
            hz[i] = make_float4(0.f, 0.f, 0.f, 0.f);
    }
    const uint32_t mb_base = smem_u32(&mbar[0]);
    const uint32_t hbase   = smem_u32(hbuf);
    const uint32_t obase   = smem_u32(&out_s[0][0][0][0]);
    if (tid < 4) {
        mbar_init(mb_base + (uint32_t)tid * 8u, 1);
        mbar_expect_tx(mb_base + (uint32_t)tid * 8u, 8192u);
    }
    __syncthreads();
    cluster_sync_full();

    uint32_t my_mb[2][2];
    #pragma unroll
    for (int g = 0; g < 2; g++)
        #pragma unroll
        for (int b = 0; b < 2; b++)
            my_mb[g][b] = mb_base + (uint32_t)((g * 2 + b)) * 8u;
    int par[2][2] = {{0, 0}, {0, 0}};

    // engine copy targets (tid < 8): peer q = tid, chunk = rank r
    uint32_t dst_q = 0;
    uint32_t rmb[2][2];
    if (tid < 8) {
        const uint32_t q = (uint32_t)tid;
        dst_q = mapa_u32(hbase, q) + (uint32_t)r * CH_STRIDE;
        #pragma unroll
        for (int g = 0; g < 2; g++)
            #pragma unroll
            for (int b = 0; b < 2; b++)
                rmb[g][b] = mapa_u32(mb_base + (uint32_t)((g * 2 + b)) * 8u, q);
    }

    // xp / ys pointers for lead lanes: base per group, batch stride TTHH
    const float* xpg[2];
    float*       ysg[2];
    #pragma unroll
    for (int g = 0; g < 2; g++) {
        xpg[g] = &xp[((size_t)(bg + g * 4) * TT) * HH + jbase + col];
        ysg[g] = &ys[((size_t)(bg + g * 4) * TT) * HH + jbase + col];
    }

    // consumer base pointers for this lane's two k-chunks (per g, per buf)
    // chunk ids: 2*kq, 2*kq+1
    const char* hA[2][2];
    const char* hB[2][2];
    #pragma unroll
    for (int g = 0; g < 2; g++)
        #pragma unroll
        for (int b = 0; b < 2; b++) {
            hA[g][b] = hbuf + g * GRP_STRIDE + b * BUF_STRIDE + (2 * kq) * CH_STRIDE;
            hB[g][b] = hA[g][b] + CH_STRIDE;
        }

    for (int t = 0; t < TT; t++) {
        const int os   = t & 1;
        const int wbuf = os ^ 1;
        const bool push = (t + 1 < TT);

        // gate on phase-A xproj availability (launch 0 only)
        if (gateA && (t & 127) == 0) {
            if (tid == 0) {
                while (((volatile int*)g_dA)[t >> 7] < 256)
                    __nanosleep(128);
                __threadfence();
            }
            __syncthreads();
        }

        // prefetch xp for this step (lead lanes)
        float xpv[2][4];
        if (lead) {
            #pragma unroll
            for (int g = 0; g < 2; g++)
                #pragma unroll
                for (int b = 0; b < 4; b++)
                    xpv[g][b] = __ldg(xpg[g] + (size_t)b * TTHH);
        }

        #pragma unroll
        for (int g = 0; g < 2; g++) {
            // ---- wait for all 8 chunks of group g (skip t=0: zeros) ----
            if (t > 0) {
                mbar_wait_cluster(my_mb[g][os], par[g][os]);
                if (tid == 0) mbar_expect_tx(my_mb[g][os], 8192u);
                par[g][os] ^= 1;
            }

            // ---- per-lane GEMV: 1 col x 4 batches x 128 k, W in regs ----
            const ull2* cA = (const ull2*)(os ? hA[g][1] : hA[g][0]);
            const ull2* cB = (const ull2*)(os ? hB[g][1] : hB[g][0]);
            float sb[4];
            #pragma unroll
            for (int b = 0; b < 4; b++) {
                u64 a = 0ull;
                #pragma unroll
                for (int i = 0; i < 16; i++) {
                    ull2 hv = cA[b * 16 + i];
                    fma2(a, w[2 * i],     hv.x);
                    fma2(a, w[2 * i + 1], hv.y);
                }
                #pragma unroll
                for (int i = 0; i < 16; i++) {
                    ull2 hv = cB[b * 16 + i];
                    fma2(a, w[32 + 2 * i],     hv.x);
                    fma2(a, w[32 + 2 * i + 1], hv.y);
                }
                float2 p = upk2(a);
                sb[b] = p.x + p.y;
            }

            // ---- in-warp reduce over kq (4 lanes) ----
            #pragma unroll
            for (int b = 0; b < 4; b++)
                sb[b] += __shfl_xor_sync(0xffffffffu, sb[b], 1);
            #pragma unroll
            for (int b = 0; b < 4; b++)
                sb[b] += __shfl_xor_sync(0xffffffffu, sb[b], 2);

            // ---- lead lanes: xp add, relu, stage + global write ----
            if (lead) {
                #pragma unroll
                for (int b = 0; b < 4; b++) {
                    float s = fmaxf(sb[b] + xpv[g][b], 0.f);
                    out_s[g][os][b][col] = s;
                    ysg[g][(size_t)b * TTHH] = s;
                }
            }
            __syncthreads();   // all warps' out_s staged before copy reads it

            // ---- async bulk push: 8 threads, 1KB to each peer ----
            if (push && tid < 8) {
                fence_proxy_async_cta();
                bulk_copy_cluster(dst_q + (uint32_t)g * GRP_STRIDE
                                        + (uint32_t)wbuf * BUF_STRIDE,
                                  obase + (uint32_t)(g * 2 + os) * 1024u,
                                  1024u, rmb[g][wbuf]);
            }
        }

        // publish recurrence progress every 32 steps
        if ((t & 31) == 31 && tid == 0) {
            __threadfence();
            ((volatile int*)g_prog)[cl * 8 + r] = t + 1;
        }

        xpg[0] += HH; xpg[1] += HH;
        ysg[0] += HH; ysg[1] += HH;
    }

    cluster_sync_full();

    // join the phase-B job queue to absorb the tail
    if (flags & F_HAVEB)
        run_phaseB(ys, WihB, biB, bhB, CB, As2, Bs2);
}

// =======================================================================
__global__ void reset_counters() {
    const int i = threadIdx.x;
    if (i == 0) { g_jcA = 0; g_jcB = 0; }
    if (i < 4) g_dA[i] = 0;
    if (i < 64) g_prog[i] = 0;
}

// =======================================================================
__global__ void proj_kernel(const float* __restrict__ ys,
                            const float* __restrict__ Wout,
                            const float* __restrict__ bout,
                            float* __restrict__ out)
{
    const int b    = blockIdx.x;
    const int c    = threadIdx.y;
    const int lane = threadIdx.x;
    const float* hrow = &ys[((size_t)b * TT + (TT - 1)) * HH];
    const float* wrow = &Wout[(size_t)c * HH];
    float s = 0.f;
    for (int k = lane; k < HH; k += 32) s += hrow[k] * wrow[k];
    #pragma unroll
    for (int o = 16; o > 0; o >>= 1) s += __shfl_down_sync(0xffffffffu, s, o);
    if (lane == 0) out[b * NCLS + c] = s + bout[c];
}

// =======================================================================
extern "C" void kernel_launch(void* const* d_in, const int* in_sizes, int n_in,
                              void* d_out, int out_size)
{
    (void)in_sizes; (void)n_in; (void)out_size;
    const float* x    = (const float*)d_in[0];
    const float* Wih[3] = {(const float*)d_in[1], (const float*)d_in[5], (const float*)d_in[9]};
    const float* Whh[3] = {(const float*)d_in[2], (const float*)d_in[6], (const float*)d_in[10]};
    const float* bih[3] = {(const float*)d_in[3], (const float*)d_in[7], (const float*)d_in[11]};
    const float* bhh[3] = {(const float*)d_in[4], (const float*)d_in[8], (const float*)d_in[12]};
    const float* Wout = (const float*)d_in[13];
    const float* bout = (const float*)d_in[14];
    float* out = (float*)d_out;

    float *xpA = nullptr, *xpB = nullptr, *ysPtr = nullptr;
    cudaGetSymbolAddress((void**)&xpA, g_xpA);
    cudaGetSymbolAddress((void**)&xpB, g_xpB);
    cudaGetSymbolAddress((void**)&ysPtr, g_ys);

    // Layer 0: phase A computes xp0 from x (gating rnn0), phase B computes
    // xp1 from ys0 as it is produced.
    reset_counters<<<1, 64>>>();
    mega<<<144, 256>>>(xpA, Whh[0], ysPtr,
                       x, Wih[0], bih[0], bhh[0], xpA, II,
                       Wih[1], bih[1], bhh[1], xpB,
                       F_HAVEA | F_HAVEB | F_GATEA);

    // Layer 1: xp1 ready; phase B computes xp2 from ys1.
    reset_counters<<<1, 64>>>();
    mega<<<144, 256>>>(xpB, Whh[1], ysPtr,
                       nullptr, nullptr, nullptr, nullptr, nullptr, 0,
                       Wih[2], bih[2], bhh[2], xpA,
                       F_HAVEB);

    // Layer 2: recurrence only.
    mega<<<64, 256>>>(xpA, Whh[2], ysPtr,
                      nullptr, nullptr, nullptr, nullptr, nullptr, 0,
                      nullptr, nullptr, nullptr, nullptr,
                      0);

    proj_kernel<<<64, dim3(32, 5)>>>(ysPtr, Wout, bout, out);
}

// round 15
// speedup vs baseline: 1.8045x; 1.8045x over previous
#include <cuda_runtime.h>
#include <cstdint>
#include <cstddef>

#define BB 64
#define TT 512
#define II 128
#define HH 512
#define NCLS 5

#define F_HAVEA 1
#define F_HAVEB 2
#define F_GATEA 4

#define TTHH ((size_t)TT * HH)

typedef unsigned long long u64;
typedef ulonglong2 ull2;

// ---------------- dynamic smem layout (rnn view) ----------------
// [0, 131072)      Wsh: u64[256 kpair][64 col]   (aliases gemm As2/Bs2)
// [131072, 163840) h_s: [g2][buf2][chunk8][1KB]
// [163840, 180224) redv: [g2][chunk8][batch4][col64] floats
// [180224, 184320) out_s: [g2][buf2][batch4][col64] floats
// [184320, 184576) mbar: 32 x u64
#define SM_W     0
#define SM_HS    131072
#define SM_REDV  163840
#define SM_OUT   180224
#define SM_MBAR  184320
#define SM_TOTAL 184576

// Scratch — static __device__ arrays per allocation rules.
__device__ float g_xpA[(size_t)BB * TT * HH];
__device__ float g_xpB[(size_t)BB * TT * HH];
__device__ float g_ys[(size_t)BB * TT * HH];

// Cross-CTA coordination (reset by reset_counters before every mega launch).
__device__ int g_jcA;         // phase-A job queue head
__device__ int g_jcB;         // phase-B job queue head
__device__ int g_dA[4];       // phase-A completed-jobs count per t-block
__device__ int g_prog[128];   // [group2][cluster8][rank8] recurrence progress

// ---------------- packed f32x2 helpers ----------------
__device__ __forceinline__ u64 pk2(float x, float y) {
    u64 r; asm("mov.b64 %0, {%1,%2};" : "=l"(r) : "f"(x), "f"(y)); return r;
}
__device__ __forceinline__ float2 upk2(u64 v) {
    float2 f; asm("mov.b64 {%0,%1}, %2;" : "=f"(f.x), "=f"(f.y) : "l"(v)); return f;
}
__device__ __forceinline__ void fma2(u64 &d, u64 a, u64 b) {
    asm("fma.rn.f32x2 %0, %1, %2, %0;" : "+l"(d) : "l"(a), "l"(b));
}

// ---------------- cluster / mbarrier helpers ----------------
__device__ __forceinline__ uint32_t smem_u32(const void* p) {
    uint32_t a;
    asm("{ .reg .u64 t; cvta.to.shared.u64 t, %1; cvt.u32.u64 %0, t; }"
        : "=r"(a) : "l"(p));
    return a;
}
__device__ __forceinline__ uint32_t mapa_u32(uint32_t local, uint32_t rank) {
    uint32_t r;
    asm("mapa.shared::cluster.u32 %0, %1, %2;" : "=r"(r) : "r"(local), "r"(rank));
    return r;
}
__device__ __forceinline__ void mbar_init(uint32_t addr, uint32_t count) {
    asm volatile("mbarrier.init.shared.b64 [%0], %1;" :: "r"(addr), "r"(count) : "memory");
}
__device__ __forceinline__ void mbar_expect_tx(uint32_t addr, uint32_t bytes) {
    asm volatile("mbarrier.arrive.expect_tx.shared.b64 _, [%0], %1;"
                 :: "r"(addr), "r"(bytes) : "memory");
}
__device__ __forceinline__ void bulk_copy_cluster(uint32_t dst_cluster, uint32_t src_cta,
                                                  uint32_t bytes, uint32_t mbar_cluster) {
    asm volatile("cp.async.bulk.shared::cluster.shared::cta.mbarrier::complete_tx::bytes "
                 "[%0], [%1], %2, [%3];"
                 :: "r"(dst_cluster), "r"(src_cta), "r"(bytes), "r"(mbar_cluster) : "memory");
}
__device__ __forceinline__ void mbar_wait_cluster(uint32_t addr, uint32_t parity) {
    asm volatile(
        "{\n\t"
        ".reg .pred P;\n\t"
        "WLP%=:\n\t"
        "mbarrier.try_wait.parity.acquire.cluster.shared::cta.b64 P, [%0], %1, 0x989680;\n\t"
        "@P bra WDN%=;\n\t"
        "bra WLP%=;\n\t"
        "WDN%=:\n\t"
        "}"
        :: "r"(addr), "r"(parity) : "memory");
}
__device__ __forceinline__ void fence_proxy_async_cta() {
    asm volatile("fence.proxy.async.shared::cta;" ::: "memory");
}
__device__ __forceinline__ void cluster_sync_full() {
    asm volatile("barrier.cluster.arrive.aligned;" ::: "memory");
    asm volatile("barrier.cluster.wait.aligned;" ::: "memory");
}
__device__ __forceinline__ void team_bar(int id) {
    asm volatile("bar.sync %0, 256;" :: "r"(id) : "memory");
}

// =======================================================================
// One 128x128 GEMM tile (512 threads): C = A @ W^T + b1 + b2.
// A row stride K, W row stride K, C row stride HH. acc 4x8 per thread.
// =======================================================================
__device__ __forceinline__ void gemm_tile(
    const float* __restrict__ A, const float* __restrict__ W,
    const float* __restrict__ b1, const float* __restrict__ b2,
    float* __restrict__ C, int K,
    u64 (*As2)[128], u64 (*Bs2)[128])
{
    const int tid = threadIdx.x;
    const int tx  = tid & 15;      // col = tx + 16*j
    const int ty  = tid >> 4;      // row = ty + 32*i  (ty 0..31)
    const int r0  = tid >> 2;      // loader row 0..127
    const int kq0 = tid & 3;       // float4 chunk along k

    u64 acc[4][8];
    #pragma unroll
    for (int i = 0; i < 4; i++)
        #pragma unroll
        for (int j = 0; j < 8; j++) acc[i][j] = 0ull;

    const float* pa = &A[(size_t)r0 * K + kq0 * 4];
    const float* pw = &W[(size_t)r0 * K + kq0 * 4];

    const int ktiles = K >> 4;
    float4 a0 = *(const float4*)pa;
    float4 w0 = *(const float4*)pw;

    for (int kt = 0; kt < ktiles; kt++) {
        __syncthreads();
        As2[kq0 * 2][r0]     = pk2(a0.x, a0.y);
        As2[kq0 * 2 + 1][r0] = pk2(a0.z, a0.w);
        Bs2[kq0 * 2][r0]     = pk2(w0.x, w0.y);
        Bs2[kq0 * 2 + 1][r0] = pk2(w0.z, w0.w);
        __syncthreads();

        if (kt + 1 < ktiles) {
            const int kb = (kt + 1) * 16;
            a0 = *(const float4*)(pa + kb);
            w0 = *(const float4*)(pw + kb);
        }

        #pragma unroll
        for (int k2 = 0; k2 < 8; k2++) {
            u64 af[4], bf[8];
            #pragma unroll
            for (int i = 0; i < 4; i++) af[i] = As2[k2][ty + 32 * i];
            #pragma unroll
            for (int j = 0; j < 8; j++) bf[j] = Bs2[k2][tx + 16 * j];
            #pragma unroll
            for (int i = 0; i < 4; i++)
                #pragma unroll
                for (int j = 0; j < 8; j++)
                    fma2(acc[i][j], af[i], bf[j]);
        }
    }

    float bias8[8];
    #pragma unroll
    for (int j = 0; j < 8; j++) {
        int n = tx + 16 * j;
        bias8[j] = b1[n] + b2[n];
    }
    #pragma unroll
    for (int i = 0; i < 4; i++) {
        const size_t m = (size_t)(ty + 32 * i);
        #pragma unroll
        for (int j = 0; j < 8; j++) {
            float2 p = upk2(acc[i][j]);
            C[m * HH + tx + 16 * j] = p.x + p.y + bias8[j];
        }
    }
}

// Run phase-B jobs (xproj of next layer from ys, K=512, gated on g_prog).
__device__ void run_phaseB(const float* __restrict__ ys,
                           const float* __restrict__ WihB,
                           const float* __restrict__ biB,
                           const float* __restrict__ bhB,
                           float* __restrict__ CB,
                           u64 (*As2)[128], u64 (*Bs2)[128])
{
    __shared__ int s_job;
    for (;;) {
        if (threadIdx.x == 0)
            s_job = atomicAdd(&g_jcB, 1);
        __syncthreads();
        const int j = s_job;
        if (j >= 1024) break;
        const int tb = j >> 8, r8 = j & 255, b = r8 >> 2, nt = r8 & 3;
        const int thr = tb * 128 + 128;
        if (threadIdx.x == 0) {
            const int grp = (b >> 2) & 1;               // group owning batch b
            volatile int* p = (volatile int*)&g_prog[grp * 64 + (b >> 3) * 8];
            #pragma unroll
            for (int q = 0; q < 8; q++)
                while (p[q] < thr) __nanosleep(128);
            __threadfence();
        }
        __syncthreads();
        gemm_tile(ys + (size_t)(b * TT + tb * 128) * HH,
                  WihB + (size_t)(nt * 128) * HH,
                  biB + nt * 128, bhB + nt * 128,
                  CB + (size_t)(b * TT + tb * 128) * HH + nt * 128,
                  HH, As2, Bs2);
        __syncthreads();
    }
}

// =======================================================================
// Mega kernel, 512 threads: clusters 0..7 = recurrence, >=8 = GEMM workers.
// Recurrence: TWO WARP-SPECIALIZED TEAMS (256 threads each) run the two
// batch groups CONCURRENTLY — team g executes R9's group-g schedule with
// named barriers; W_hh lives in shared memory (one copy, both teams).
// Exchange = R9 bulk-engine 1KB copies with per-chunk tx-counted mbarriers.
// =======================================================================
__global__ void __launch_bounds__(512, 1) __cluster_dims__(8, 1, 1)
mega(const float* __restrict__ xp, const float* __restrict__ Whh,
     float* __restrict__ ys,
     const float* __restrict__ Ax,  const float* __restrict__ WihA,
     const float* __restrict__ biA, const float* __restrict__ bhA,
     float* __restrict__ CA, int KA,
     const float* __restrict__ WihB, const float* __restrict__ biB,
     const float* __restrict__ bhB,  float* __restrict__ CB,
     int flags)
{
    extern __shared__ char dsm[];
    u64 (*As2)[128] = (u64(*)[128])(dsm);
    u64 (*Bs2)[128] = (u64(*)[128])(dsm + 8192);

    const int tid = threadIdx.x;
    const int cl  = blockIdx.x >> 3;

    // =================== phase A: all CTAs drain the queue ===================
    if (flags & F_HAVEA) {
        __shared__ int s_job;
        for (;;) {
            if (tid == 0) s_job = atomicAdd(&g_jcA, 1);
            __syncthreads();
            const int j = s_job;
            if (j >= 1024) break;
            const int tb = j >> 8, r8 = j & 255, b = r8 >> 2, nt = r8 & 3;
            gemm_tile(Ax + (size_t)(b * TT + tb * 128) * KA,
                      WihA + (size_t)(nt * 128) * KA,
                      biA + nt * 128, bhA + nt * 128,
                      CA + (size_t)(b * TT + tb * 128) * HH + nt * 128,
                      KA, As2, Bs2);
            __syncthreads();
            __threadfence();
            if (tid == 0) atomicAdd(&g_dA[tb], 1);
            __syncthreads();
        }
        __syncthreads();   // As2/Bs2 dead before rnn CTAs overwrite with W
    }

    if (cl >= 8) {
        if (flags & F_HAVEB)
            run_phaseB(ys, WihB, biB, bhB, CB, As2, Bs2);
        return;
    }

    // ======================= recurrence role =======================
    const int r     = blockIdx.x & 7;
    const int bg    = cl * 8;
    const int jbase = r * 64;
    const bool gateA = (flags & F_GATEA) != 0;

    u64*   Wsh   = (u64*)(dsm + SM_W);        // [kpair 256][col 64]
    float* redv  = (float*)(dsm + SM_REDV);   // [g][chunk][batch][col]
    float* out_s = (float*)(dsm + SM_OUT);    // [g][buf][batch][col]

    // ---- load W_hh slice into smem: thread -> (col = tid>>3, kseg = tid&7) ----
    {
        const int col  = tid >> 3;
        const int kseg = tid & 7;
        const float* wrow = &Whh[(size_t)(jbase + col) * HH + kseg * 64];
        #pragma unroll
        for (int i = 0; i < 16; i++) {
            float4 v = *(const float4*)&wrow[i * 4];
            const int kp = kseg * 32 + i * 2;
            Wsh[(size_t)kp * 64 + col]       = pk2(v.x, v.y);
            Wsh[(size_t)(kp + 1) * 64 + col] = pk2(v.z, v.w);
        }
    }

    // ---- zero h buffers; init 32 mbarriers + first expects ----
    {
        float4* hz = (float4*)(dsm + SM_HS);
        for (int i = tid; i < 32768 / 16; i += 512)
            hz[i] = make_float4(0.f, 0.f, 0.f, 0.f);
    }
    const uint32_t mb_base = smem_u32(dsm + SM_MBAR);
    const uint32_t hbase   = smem_u32(dsm + SM_HS);
    const uint32_t obase   = smem_u32(dsm + SM_OUT);
    if (tid < 32) {   // idx = (g*2+buf)*8 + chunk
        mbar_init(mb_base + (uint32_t)tid * 8u, 1);
        mbar_expect_tx(mb_base + (uint32_t)tid * 8u, 1024u);
    }
    __syncthreads();
    cluster_sync_full();

    // ---- team split ----
    const int g     = tid >> 8;          // team / batch group
    const int ttid  = tid & 255;
    const int kc    = ttid >> 5;         // warp's k-chunk
    const int jp    = ttid & 31;
    const int barid = g + 1;

    uint32_t my_mb[2];
    #pragma unroll
    for (int b = 0; b < 2; b++)
        my_mb[b] = mb_base + (uint32_t)(((g * 2 + b) * 8 + kc)) * 8u;
    int par[2] = {0, 0};

    // copy issuers: team-local ttid<8, peer q = ttid
    uint32_t dst_q = 0;
    uint32_t rmb[2];
    if (ttid < 8) {
        const uint32_t q = (uint32_t)ttid;
        dst_q = mapa_u32(hbase, q) + (uint32_t)g * 16384u + (uint32_t)r * 1024u;
        #pragma unroll
        for (int b = 0; b < 2; b++)
            rmb[b] = mapa_u32(mb_base + (uint32_t)(((g * 2 + b) * 8 + r)) * 8u, q);
    }

    // reduce mapping
    const int cb = ttid >> 6;
    const int cj = ttid & 63;
    const float* xp_p = &xp[((size_t)(bg + g * 4 + cb) * TT) * HH + jbase + cj];
    float*       ys_p = &ys[((size_t)(bg + g * 4 + cb) * TT) * HH + jbase + cj];

    // W smem base for this warp's chunk; cols jp / jp+32
    const u64* wps = Wsh + (size_t)(kc * 32) * 64;
    // h base for this warp's chunk (bytes)
    const char* hgb = dsm + SM_HS + g * 16384 + kc * 1024;
    float* myredv = redv + (g * 8 + kc) * 256;          // [batch4][col... jp slots]
    float* grpredv = redv + g * 2048;

    for (int t = 0; t < TT; t++) {
        const int os   = t & 1;
        const int wbuf = os ^ 1;
        const bool push = (t + 1 < TT);

        // gate on phase-A xproj availability (launch 0 only)
        if (gateA && (t & 127) == 0) {
            if (ttid == 0) {
                while (((volatile int*)g_dA)[t >> 7] < 256)
                    __nanosleep(128);
                __threadfence();
            }
            team_bar(barid);
        }

        const float xpv = __ldg(xp_p);

        // ---- per-warp wait for MY chunk (skip t=0: zeros) ----
        if (t > 0) {
            mbar_wait_cluster(my_mb[os], par[os]);
            if (jp == 0) mbar_expect_tx(my_mb[os], 1024u);
            par[os] ^= 1;
        }

        // ---- partial GEMV: W from smem, h broadcast from smem ----
        const ull2* hb = (const ull2*)(hgb + os * 8192);
        u64 acc0[4], acc1[4];
        #pragma unroll
        for (int b = 0; b < 4; b++) { acc0[b] = 0ull; acc1[b] = 0ull; }
        #pragma unroll
        for (int kv = 0; kv < 16; kv++) {
            const u64 w00 = wps[(size_t)(2 * kv) * 64 + jp];
            const u64 w01 = wps[(size_t)(2 * kv + 1) * 64 + jp];
            const u64 w10 = wps[(size_t)(2 * kv) * 64 + 32 + jp];
            const u64 w11 = wps[(size_t)(2 * kv + 1) * 64 + 32 + jp];
            #pragma unroll
            for (int b = 0; b < 4; b++) {
                ull2 hv = hb[b * 16 + kv];
                fma2(acc0[b], w00, hv.x);
                fma2(acc0[b], w01, hv.y);
                fma2(acc1[b], w10, hv.x);
                fma2(acc1[b], w11, hv.y);
            }
        }

        #pragma unroll
        for (int b = 0; b < 4; b++) {
            float2 p0 = upk2(acc0[b]);
            float2 p1 = upk2(acc1[b]);
            myredv[b * 64 + jp]      = p0.x + p0.y;
            myredv[b * 64 + jp + 32] = p1.x + p1.y;
        }
        team_bar(barid);

        // ---- reduce 8 chunks + xproj + relu ----
        {
            float s = xpv;
            #pragma unroll
            for (int c = 0; c < 8; c++) s += grpredv[(c * 4 + cb) * 64 + cj];
            s = fmaxf(s, 0.f);
            out_s[((g * 2 + os) * 4 + cb) * 64 + cj] = s;
            *ys_p = s;
            ys_p += HH;
        }
        team_bar(barid);

        // ---- async bulk push: 8 threads, 1KB to each peer ----
        if (push && ttid < 8) {
            fence_proxy_async_cta();
            bulk_copy_cluster(dst_q + (uint32_t)wbuf * 8192u,
                              obase + (uint32_t)(g * 2 + os) * 1024u,
                              1024u, rmb[wbuf]);
        }

        // publish per-group recurrence progress every 32 steps
        if ((t & 31) == 31 && ttid == 0) {
            __threadfence();
            ((volatile int*)g_prog)[g * 64 + cl * 8 + r] = t + 1;
        }

        xp_p += HH;
    }

    __syncthreads();       // rejoin teams
    cluster_sync_full();   // all inbound DSMEM traffic settled

    // join the phase-B job queue to absorb the tail
    if (flags & F_HAVEB)
        run_phaseB(ys, WihB, biB, bhB, CB, As2, Bs2);
}

// =======================================================================
__global__ void reset_counters() {
    const int i = threadIdx.x;
    if (i == 0) { g_jcA = 0; g_jcB = 0; }
    if (i < 4) g_dA[i] = 0;
    if (i < 128) g_prog[i] = 0;
}

// =======================================================================
__global__ void proj_kernel(const float* __restrict__ ys,
                            const float* __restrict__ Wout,
                            const float* __restrict__ bout,
                            float* __restrict__ out)
{
    const int b    = blockIdx.x;
    const int c    = threadIdx.y;
    const int lane = threadIdx.x;
    const float* hrow = &ys[((size_t)b * TT + (TT - 1)) * HH];
    const float* wrow = &Wout[(size_t)c * HH];
    float s = 0.f;
    for (int k = lane; k < HH; k += 32) s += hrow[k] * wrow[k];
    #pragma unroll
    for (int o = 16; o > 0; o >>= 1) s += __shfl_down_sync(0xffffffffu, s, o);
    if (lane == 0) out[b * NCLS + c] = s + bout[c];
}

// =======================================================================
extern "C" void kernel_launch(void* const* d_in, const int* in_sizes, int n_in,
                              void* d_out, int out_size)
{
    (void)in_sizes; (void)n_in; (void)out_size;
    const float* x    = (const float*)d_in[0];
    const float* Wih[3] = {(const float*)d_in[1], (const float*)d_in[5], (const float*)d_in[9]};
    const float* Whh[3] = {(const float*)d_in[2], (const float*)d_in[6], (const float*)d_in[10]};
    const float* bih[3] = {(const float*)d_in[3], (const float*)d_in[7], (const float*)d_in[11]};
    const float* bhh[3] = {(const float*)d_in[4], (const float*)d_in[8], (const float*)d_in[12]};
    const float* Wout = (const float*)d_in[13];
    const float* bout = (const float*)d_in[14];
    float* out = (float*)d_out;

    float *xpA = nullptr, *xpB = nullptr, *ysPtr = nullptr;
    cudaGetSymbolAddress((void**)&xpA, g_xpA);
    cudaGetSymbolAddress((void**)&xpB, g_xpB);
    cudaGetSymbolAddress((void**)&ysPtr, g_ys);

    cudaFuncSetAttribute(mega, cudaFuncAttributeMaxDynamicSharedMemorySize, SM_TOTAL);

    // Layer 0: phase A computes xp0 from x (gating rnn0); phase B computes
    // xp1 from ys0 as it is produced.
    reset_counters<<<1, 128>>>();
    mega<<<144, 512, SM_TOTAL>>>(xpA, Whh[0], ysPtr,
                                 x, Wih[0], bih[0], bhh[0], xpA, II,
                                 Wih[1], bih[1], bhh[1], xpB,
                                 F_HAVEA | F_HAVEB | F_GATEA);

    // Layer 1: xp1 ready; phase B computes xp2 from ys1.
    reset_counters<<<1, 128>>>();
    mega<<<144, 512, SM_TOTAL>>>(xpB, Whh[1], ysPtr,
                                 nullptr, nullptr, nullptr, nullptr, nullptr, 0,
                                 Wih[2], bih[2], bhh[2], xpA,
                                 F_HAVEB);

    // Layer 2: recurrence only.
    mega<<<64, 512, SM_TOTAL>>>(xpA, Whh[2], ysPtr,
                                nullptr, nullptr, nullptr, nullptr, nullptr, 0,
                                nullptr, nullptr, nullptr, nullptr,
                                0);

    proj_kernel<<<64, dim3(32, 5)>>>(ysPtr, Wout, bout, out);
}

// round 16
// speedup vs baseline: 1.8848x; 1.0445x over previous
#include <cuda_runtime.h>
#include <cstdint>
#include <cstddef>

#define BB 64
#define TT 512
#define II 128
#define HH 512
#define NCLS 5

#define F_HAVEA 1
#define F_HAVEB 2
#define F_GATEA 4

typedef unsigned long long u64;
typedef ulonglong2 ull2;

// Scratch — static __device__ arrays per allocation rules.
__device__ float g_xpA[(size_t)BB * TT * HH];
__device__ float g_xpB[(size_t)BB * TT * HH];
__device__ float g_ys[(size_t)BB * TT * HH];

// Cross-CTA coordination (reset by reset_counters before every mega launch).
__device__ int g_jcA;        // phase-A job queue head
__device__ int g_jcB;        // phase-B job queue head
__device__ int g_dA[4];      // phase-A completed-jobs count per t-block
__device__ int g_prog[64];   // recurrence progress per (cluster, rank)

// ---------------- packed f32x2 helpers ----------------
__device__ __forceinline__ u64 pk2(float x, float y) {
    u64 r; asm("mov.b64 %0, {%1,%2};" : "=l"(r) : "f"(x), "f"(y)); return r;
}
__device__ __forceinline__ float2 upk2(u64 v) {
    float2 f; asm("mov.b64 {%0,%1}, %2;" : "=f"(f.x), "=f"(f.y) : "l"(v)); return f;
}
__device__ __forceinline__ void fma2(u64 &d, u64 a, u64 b) {
    asm("fma.rn.f32x2 %0, %1, %2, %0;" : "+l"(d) : "l"(a), "l"(b));
}

// ---------------- cluster / mbarrier helpers ----------------
__device__ __forceinline__ uint32_t smem_u32(const void* p) {
    uint32_t a;
    asm("{ .reg .u64 t; cvta.to.shared.u64 t, %1; cvt.u32.u64 %0, t; }"
        : "=r"(a) : "l"(p));
    return a;
}
__device__ __forceinline__ uint32_t mapa_u32(uint32_t local, uint32_t rank) {
    uint32_t r;
    asm("mapa.shared::cluster.u32 %0, %1, %2;" : "=r"(r) : "r"(local), "r"(rank));
    return r;
}
__device__ __forceinline__ void mbar_init(uint32_t addr, uint32_t count) {
    asm volatile("mbarrier.init.shared.b64 [%0], %1;" :: "r"(addr), "r"(count) : "memory");
}
__device__ __forceinline__ void mbar_expect_tx(uint32_t addr, uint32_t bytes) {
    asm volatile("mbarrier.arrive.expect_tx.shared.b64 _, [%0], %1;"
                 :: "r"(addr), "r"(bytes) : "memory");
}
__device__ __forceinline__ void bulk_copy_cluster(uint32_t dst_cluster, uint32_t src_cta,
                                                  uint32_t bytes, uint32_t mbar_cluster) {
    asm volatile("cp.async.bulk.shared::cluster.shared::cta.mbarrier::complete_tx::bytes "
                 "[%0], [%1], %2, [%3];"
                 :: "r"(dst_cluster), "r"(src_cta), "r"(bytes), "r"(mbar_cluster) : "memory");
}
__device__ __forceinline__ void mbar_wait_cluster(uint32_t addr, uint32_t parity) {
    asm volatile(
        "{\n\t"
        ".reg .pred P;\n\t"
        "WLP%=:\n\t"
        "mbarrier.try_wait.parity.acquire.cluster.shared::cta.b64 P, [%0], %1, 0x989680;\n\t"
        "@P bra WDN%=;\n\t"
        "bra WLP%=;\n\t"
        "WDN%=:\n\t"
        "}"
        :: "r"(addr), "r"(parity) : "memory");
}
__device__ __forceinline__ void fence_proxy_async_cta() {
    asm volatile("fence.proxy.async.shared::cta;" ::: "memory");
}
__device__ __forceinline__ void cluster_sync_full() {
    asm volatile("barrier.cluster.arrive.aligned;" ::: "memory");
    asm volatile("barrier.cluster.wait.aligned;" ::: "memory");
}

// =======================================================================
// One 128x128 GEMM tile: C = A[0:128,0:K] @ W[0:128,0:K]^T + b1 + b2.
// =======================================================================
__device__ __forceinline__ void gemm_tile(
    const float* __restrict__ A, const float* __restrict__ W,
    const float* __restrict__ b1, const float* __restrict__ b2,
    float* __restrict__ C, int K,
    u64 (*As2)[128], u64 (*Bs2)[128])
{
    const int tid = threadIdx.x;
    const int tx = tid & 15;
    const int ty = tid >> 4;
    const int r0  = tid >> 2;
    const int kq0 = tid & 3;

    u64 acc[8][8];
    #pragma unroll
    for (int i = 0; i < 8; i++)
        #pragma unroll
        for (int j = 0; j < 8; j++) acc[i][j] = 0ull;

    const float* pa0 = &A[(size_t)r0        * K + kq0 * 4];
    const float* pa1 = &A[(size_t)(64 + r0) * K + kq0 * 4];
    const float* pw0 = &W[(size_t)r0        * K + kq0 * 4];
    const float* pw1 = &W[(size_t)(64 + r0) * K + kq0 * 4];

    const int ktiles = K >> 4;
    float4 a0 = *(const float4*)pa0;
    float4 a1 = *(const float4*)pa1;
    float4 w0 = *(const float4*)pw0;
    float4 w1 = *(const float4*)pw1;

    for (int kt = 0; kt < ktiles; kt++) {
        __syncthreads();
        As2[kq0 * 2][r0]          = pk2(a0.x, a0.y);
        As2[kq0 * 2 + 1][r0]      = pk2(a0.z, a0.w);
        As2[kq0 * 2][64 + r0]     = pk2(a1.x, a1.y);
        As2[kq0 * 2 + 1][64 + r0] = pk2(a1.z, a1.w);
        Bs2[kq0 * 2][r0]          = pk2(w0.x, w0.y);
        Bs2[kq0 * 2 + 1][r0]      = pk2(w0.z, w0.w);
        Bs2[kq0 * 2][64 + r0]     = pk2(w1.x, w1.y);
        Bs2[kq0 * 2 + 1][64 + r0] = pk2(w1.z, w1.w);
        __syncthreads();

        if (kt + 1 < ktiles) {
            const int kb = (kt + 1) * 16;
            a0 = *(const float4*)(pa0 + kb);
            a1 = *(const float4*)(pa1 + kb);
            w0 = *(const float4*)(pw0 + kb);
            w1 = *(const float4*)(pw1 + kb);
        }

        #pragma unroll
        for (int k2 = 0; k2 < 8; k2++) {
            u64 af[8], bf[8];
            #pragma unroll
            for (int i = 0; i < 8; i++) af[i] = As2[k2][ty + 16 * i];
            #pragma unroll
            for (int j = 0; j < 8; j++) bf[j] = Bs2[k2][tx + 16 * j];
            #pragma unroll
            for (int i = 0; i < 8; i++)
                #pragma unroll
                for (int j = 0; j < 8; j++)
                    fma2(acc[i][j], af[i], bf[j]);
        }
    }

    float bias8[8];
    #pragma unroll
    for (int j = 0; j < 8; j++) {
        int n = tx + 16 * j;
        bias8[j] = b1[n] + b2[n];
    }
    #pragma unroll
    for (int i = 0; i < 8; i++) {
        const size_t m = (size_t)(ty + 16 * i);
        #pragma unroll
        for (int j = 0; j < 8; j++) {
            float2 p = upk2(acc[i][j]);
            C[m * HH + tx + 16 * j] = p.x + p.y + bias8[j];
        }
    }
}

// Run phase-B jobs (xproj of next layer from ys, K=512, gated on g_prog).
__device__ void run_phaseB(const float* __restrict__ ys,
                           const float* __restrict__ WihB,
                           const float* __restrict__ biB,
                           const float* __restrict__ bhB,
                           float* __restrict__ CB,
                           u64 (*As2)[128], u64 (*Bs2)[128])
{
    __shared__ int s_job;
    for (;;) {
        if (threadIdx.x == 0)
            s_job = atomicAdd(&g_jcB, 1);
        __syncthreads();
        const int j = s_job;
        if (j >= 1024) break;
        const int tb = j >> 8, r8 = j & 255, b = r8 >> 2, nt = r8 & 3;
        const int thr = tb * 128 + 128;
        if (threadIdx.x == 0) {
            const int cb8 = (b >> 3) * 8;
            #pragma unroll
            for (int q = 0; q < 8; q++) {
                while (((volatile int*)g_prog)[cb8 + q] < thr)
                    __nanosleep(128);
            }
            __threadfence();
        }
        __syncthreads();
        gemm_tile(ys + (size_t)(b * TT + tb * 128) * HH,
                  WihB + (size_t)(nt * 128) * HH,
                  biB + nt * 128, bhB + nt * 128,
                  CB + (size_t)(b * TT + tb * 128) * HH + nt * 128,
                  HH, As2, Bs2);
        __syncthreads();
    }
}

// =======================================================================
// Mega kernel: clusters 0..7 = recurrence; clusters >= 8 = GEMM workers.
// Recurrence = R9 scheme with MERGED-GROUP exchange: the two 4-batch
// groups compute in one fused pass and their slices ship as ONE 2KB
// bulk copy per peer per step (8 copies/step instead of 16), halving
// the engine transaction count that paces the step.
// h_s layout: [buf][chunk][g][batch][64f] — sender slice contiguous 2KB.
// =======================================================================
__global__ void __launch_bounds__(256, 1) __cluster_dims__(8, 1, 1)
mega(const float* __restrict__ xp, const float* __restrict__ Whh,
     float* __restrict__ ys,
     const float* __restrict__ Ax,  const float* __restrict__ WihA,
     const float* __restrict__ biA, const float* __restrict__ bhA,
     float* __restrict__ CA, int KA,
     const float* __restrict__ WihB, const float* __restrict__ biB,
     const float* __restrict__ bhB,  float* __restrict__ CB,
     int flags)
{
    __shared__ ull2 h_s[2][8][2][4][16];       // [buf][chunk][g][batch][64f] 32KB
    __shared__ float redv[8][2][4][64];        // [chunk][g][batch][col] 16KB
    __shared__ __align__(16) float out_s[2][2][4][64]; // [buf][g][batch][col] 4KB
    __shared__ __align__(8) u64 mbar[2][8];    // [buf][chunk]
    __shared__ u64 As2[8][128];
    __shared__ u64 Bs2[8][128];

    const int tid = threadIdx.x;
    const int cl  = blockIdx.x >> 3;

    if (cl >= 8) {
        // ======================= GEMM role =======================
        if (flags & F_HAVEA) {
            __shared__ int s_job;
            for (;;) {
                if (tid == 0) s_job = atomicAdd(&g_jcA, 1);
                __syncthreads();
                const int j = s_job;
                if (j >= 1024) break;
                const int tb = j >> 8, r8 = j & 255, b = r8 >> 2, nt = r8 & 3;
                gemm_tile(Ax + (size_t)(b * TT + tb * 128) * KA,
                          WihA + (size_t)(nt * 128) * KA,
                          biA + nt * 128, bhA + nt * 128,
                          CA + (size_t)(b * TT + tb * 128) * HH + nt * 128,
                          KA, As2, Bs2);
                __syncthreads();
                __threadfence();
                if (tid == 0) atomicAdd(&g_dA[tb], 1);
                __syncthreads();
            }
        }
        if (flags & F_HAVEB)
            run_phaseB(ys, WihB, biB, bhB, CB, As2, Bs2);
        return;
    }

    // ======================= recurrence role =======================
    const int r     = blockIdx.x & 7;
    const int bg    = cl * 8;
    const int jbase = r * 64;
    const bool gateA = (flags & F_GATEA) != 0;

    const int jp = tid & 31;
    const int kc = tid >> 5;
    const int k0 = kc * 64;

    // ---- W_hh slice in registers, k-pair packed ----
    u64 w[2][32];
    #pragma unroll
    for (int jj = 0; jj < 2; jj++) {
        const float* wrow = &Whh[(size_t)(jbase + jp + jj * 32) * HH + k0];
        #pragma unroll
        for (int kp = 0; kp < 32; kp++) {
            float2 wv = *(const float2*)&wrow[2 * kp];
            w[jj][kp] = pk2(wv.x, wv.y);
        }
    }

    // ---- zero h buffers; init 16 mbarriers + first expects (2KB) ----
    {
        float4* hs = (float4*)h_s;
        for (int i = tid; i < 2 * 8 * 2 * 4 * 16; i += 256)
            hs[i] = make_float4(0.f, 0.f, 0.f, 0.f);
    }
    const uint32_t mb_base = smem_u32(&mbar[0][0]);
    const uint32_t hbase   = smem_u32(&h_s[0][0][0][0][0]);
    const uint32_t obase   = smem_u32(&out_s[0][0][0][0]);
    if (tid < 16) {
        mbar_init(mb_base + (uint32_t)tid * 8u, 1);
        mbar_expect_tx(mb_base + (uint32_t)tid * 8u, 2048u);
    }
    __syncthreads();
    cluster_sync_full();

    // my-warp wait mbarriers: [buf], chunk = kc
    const uint32_t my_mb[2] = { mb_base + (uint32_t)kc * 8u,
                                mb_base + (uint32_t)(8 + kc) * 8u };
    int par[2] = {0, 0};

    // copy targets (tid < 8): peer q = tid, chunk = rank r (2KB slice)
    uint32_t dst_q = 0;
    uint32_t rmb[2];
    if (tid < 8) {
        const uint32_t q = (uint32_t)tid;
        dst_q = mapa_u32(hbase, q) + (uint32_t)r * 2048u;
        #pragma unroll
        for (int b = 0; b < 2; b++)
            rmb[b] = mapa_u32(mb_base + (uint32_t)((b * 8 + r)) * 8u, q);
    }

    // reduce mapping: thread -> (batch-in-group cb, col cj), both groups
    const int cb = tid >> 6;
    const int cj = tid & 63;
    const float* xp_p[2];
    float*       ys_p[2];
    #pragma unroll
    for (int g = 0; g < 2; g++) {
        xp_p[g] = &xp[((size_t)(bg + g * 4 + cb) * TT) * HH + jbase + cj];
        ys_p[g] = &ys[((size_t)(bg + g * 4 + cb) * TT) * HH + jbase + cj];
    }

    for (int t = 0; t < TT; t++) {
        const int os   = t & 1;
        const int wbuf = os ^ 1;
        const bool push = (t + 1 < TT);

        // gate on phase-A xproj availability (launch 0 only)
        if (gateA && (t & 127) == 0) {
            if (tid == 0) {
                while (((volatile int*)g_dA)[t >> 7] < 256)
                    __nanosleep(128);
                __threadfence();
            }
            __syncthreads();
        }

        float xpv[2];
        xpv[0] = __ldg(xp_p[0]);
        xpv[1] = __ldg(xp_p[1]);

        // ---- per-warp wait for MY chunk (both groups in one 2KB arrival) ----
        if (t > 0) {
            mbar_wait_cluster(my_mb[os], par[os]);
            if (jp == 0) mbar_expect_tx(my_mb[os], 2048u);
            par[os] ^= 1;
        }

        // ---- merged GEMV: both groups, W from regs, h broadcast from smem ----
        const ull2* hb = &h_s[os][kc][0][0][0];   // [g][b][kv]
        u64 a0[2][4], a1[2][4];                   // [g][b]
        #pragma unroll
        for (int g = 0; g < 2; g++)
            #pragma unroll
            for (int b = 0; b < 4; b++) { a0[g][b] = 0ull; a1[g][b] = 0ull; }

        #pragma unroll
        for (int kv = 0; kv < 16; kv++) {
            const u64 w00 = w[0][2 * kv], w01 = w[0][2 * kv + 1];
            const u64 w10 = w[1][2 * kv], w11 = w[1][2 * kv + 1];
            #pragma unroll
            for (int g = 0; g < 2; g++)
                #pragma unroll
                for (int b = 0; b < 4; b++) {
                    ull2 hv = hb[(g * 4 + b) * 16 + kv];
                    fma2(a0[g][b], w00, hv.x);
                    fma2(a0[g][b], w01, hv.y);
                    fma2(a1[g][b], w10, hv.x);
                    fma2(a1[g][b], w11, hv.y);
                }
        }

        // ---- stage partials (both groups) ----
        #pragma unroll
        for (int g = 0; g < 2; g++)
            #pragma unroll
            for (int b = 0; b < 4; b++) {
                float2 p0 = upk2(a0[g][b]);
                float2 p1 = upk2(a1[g][b]);
                redv[kc][g][b][jp]      = p0.x + p0.y;
                redv[kc][g][b][jp + 32] = p1.x + p1.y;
            }
        __syncthreads();

        // ---- reduce 8 chunks + xproj + relu, both groups ----
        #pragma unroll
        for (int g = 0; g < 2; g++) {
            float s = xpv[g];
            #pragma unroll
            for (int c = 0; c < 8; c++) s += redv[c][g][cb][cj];
            s = fmaxf(s, 0.f);
            out_s[os][g][cb][cj] = s;
            *ys_p[g] = s;
            ys_p[g] += HH;
        }
        __syncthreads();

        // ---- ONE 2KB bulk push per peer (8 threads, 1 copy each) ----
        if (push && tid < 8) {
            fence_proxy_async_cta();
            bulk_copy_cluster(dst_q + (uint32_t)wbuf * 16384u,
                              obase + (uint32_t)os * 2048u,
                              2048u, rmb[wbuf]);
        }

        // publish recurrence progress every 32 steps
        if ((t & 31) == 31 && tid == 0) {
            __threadfence();
            ((volatile int*)g_prog)[cl * 8 + r] = t + 1;
        }

        xp_p[0] += HH;
        xp_p[1] += HH;
    }

    cluster_sync_full();

    // join the phase-B job queue to absorb the tail
    if (flags & F_HAVEB)
        run_phaseB(ys, WihB, biB, bhB, CB, As2, Bs2);
}

// =======================================================================
__global__ void reset_counters() {
    const int i = threadIdx.x;
    if (i == 0) { g_jcA = 0; g_jcB = 0; }
    if (i < 4) g_dA[i] = 0;
    if (i < 64) g_prog[i] = 0;
}

// =======================================================================
__global__ void proj_kernel(const float* __restrict__ ys,
                            const float* __restrict__ Wout,
                            const float* __restrict__ bout,
                            float* __restrict__ out)
{
    const int b    = blockIdx.x;
    const int c    = threadIdx.y;
    const int lane = threadIdx.x;
    const float* hrow = &ys[((size_t)b * TT + (TT - 1)) * HH];
    const float* wrow = &Wout[(size_t)c * HH];
    float s = 0.f;
    for (int k = lane; k < HH; k += 32) s += hrow[k] * wrow[k];
    #pragma unroll
    for (int o = 16; o > 0; o >>= 1) s += __shfl_down_sync(0xffffffffu, s, o);
    if (lane == 0) out[b * NCLS + c] = s + bout[c];
}

// =======================================================================
extern "C" void kernel_launch(void* const* d_in, const int* in_sizes, int n_in,
                              void* d_out, int out_size)
{
    (void)in_sizes; (void)n_in; (void)out_size;
    const float* x    = (const float*)d_in[0];
    const float* Wih[3] = {(const float*)d_in[1], (const float*)d_in[5], (const float*)d_in[9]};
    const float* Whh[3] = {(const float*)d_in[2], (const float*)d_in[6], (const float*)d_in[10]};
    const float* bih[3] = {(const float*)d_in[3], (const float*)d_in[7], (const float*)d_in[11]};
    const float* bhh[3] = {(const float*)d_in[4], (const float*)d_in[8], (const float*)d_in[12]};
    const float* Wout = (const float*)d_in[13];
    const float* bout = (const float*)d_in[14];
    float* out = (float*)d_out;

    float *xpA = nullptr, *xpB = nullptr, *ysPtr = nullptr;
    cudaGetSymbolAddress((void**)&xpA, g_xpA);
    cudaGetSymbolAddress((void**)&xpB, g_xpB);
    cudaGetSymbolAddress((void**)&ysPtr, g_ys);

    // Layer 0: phase A computes xp0 from x (gating rnn0), phase B computes
    // xp1 from ys0 as it is produced.
    reset_counters<<<1, 64>>>();
    mega<<<144, 256>>>(xpA, Whh[0], ysPtr,
                       x, Wih[0], bih[0], bhh[0], xpA, II,
                       Wih[1], bih[1], bhh[1], xpB,
                       F_HAVEA | F_HAVEB | F_GATEA);

    // Layer 1: xp1 ready; phase B computes xp2 from ys1.
    reset_counters<<<1, 64>>>();
    mega<<<144, 256>>>(xpB, Whh[1], ysPtr,
                       nullptr, nullptr, nullptr, nullptr, nullptr, 0,
                       Wih[2], bih[2], bhh[2], xpA,
                       F_HAVEB);

    // Layer 2: recurrence only.
    mega<<<64, 256>>>(xpA, Whh[2], ysPtr,
                      nullptr, nullptr, nullptr, nullptr, nullptr, 0,
                      nullptr, nullptr, nullptr, nullptr,
                      0);

    proj_kernel<<<64, dim3(32, 5)>>>(ysPtr, Wout, bout, out);
}